// round 14
// baseline (speedup 1.0000x reference)
#include <cuda_runtime.h>
#include <cstdint>

// HungarianMatcher cost matrix, diagonal only.
//   out[b,q,t] = |cq-ct|+|wq-wt| - softmax(logits[b,q])[label_t] - gIoU(scaled)
//
// Deep cp.async pipeline: 2 rows/warp/chunk staged in smem, exactly 2 chunks
// per block, two-stage drain. launch_bounds(256,5): all 608 blocks resident
// in a single wave (5 x 148 = 740 >= 608) -> no tail wave.

#define BS 64
#define NQ 300
#define NC 200
#define NT 32
#define THREADS 256
#define WARPS 8
#define RPW 2                              // rows per warp per chunk
#define RPC (WARPS * RPW)                  // 16 rows per chunk
#define QCHUNKS ((NQ + RPC - 1) / RPC)     // 19
#define NCHUNKS (BS * QCHUNKS)             // 1216
#define GRID (NCHUNKS / 2)                 // 608, 2 chunks per block

__global__ __launch_bounds__(THREADS, 5)
void matcher_kernel(const float* __restrict__ logits,
                    const float* __restrict__ pred_seg,
                    const float* __restrict__ tgt_seg,
                    const float* __restrict__ lengths,
                    const int*   __restrict__ labels32,
                    float* __restrict__ out)
{
    __shared__ __align__(16) float s_rows[2][WARPS][RPW][NC];   // 25.6 KB

    const int warp = threadIdx.x >> 5;
    const int lane = threadIdx.x & 31;

    // Label dtype probe on batch 0 (JAX silently demotes int64->int32).
    const int plo = labels32[2 * lane];
    const int phi = labels32[2 * lane + 1];
    const bool ok64 = (phi == 0) && ((unsigned)plo < (unsigned)NC);
    const bool is64 = (__ballot_sync(0xffffffffu, ok64) == 0xffffffffu);

    const int c0 = blockIdx.x * 2;
    const int c1 = c0 + 1;

    // ---- stage both chunks' rows via cp.async (one group per chunk) ----
    auto issue = [&](int c, int p) {
        const int bb = c / QCHUNKS;
        const int qb = (c - bb * QCHUNKS) * RPC + RPW * warp;
        #pragma unroll
        for (int r = 0; r < RPW; ++r) {
            const int q = qb + r;
            if (q < NQ) {
                const char* src =
                    (const char*)(logits + ((size_t)bb * NQ + q) * NC);
                const uint32_t d = (uint32_t)
                    __cvta_generic_to_shared(&s_rows[p][warp][r][0]);
                asm volatile("cp.async.cg.shared.global [%0], [%1], 16;\n"
                             :: "r"(d + lane * 16), "l"(src + lane * 16));
                if (lane < 18)
                    asm volatile("cp.async.cg.shared.global [%0], [%1], 16;\n"
                                 :: "r"(d + (lane + 32) * 16),
                                    "l"(src + (lane + 32) * 16));
            } else {
                // tail hygiene: zero unused staging row so speculative exps
                // read finite values (their results are never stored)
                float4* dst = (float4*)&s_rows[p][warp][r][0];
                dst[lane] = make_float4(0.f, 0.f, 0.f, 0.f);
                if (lane < 18)
                    dst[lane + 32] = make_float4(0.f, 0.f, 0.f, 0.f);
            }
        }
        asm volatile("cp.async.commit_group;\n" ::: "memory");
    };
    issue(c0, 0);
    issue(c1, 1);

    // ---- aux loads for both chunks (LDGs overlap the async copies) ----
    int   b[2], qb[2], lab[2];
    float L[2];
    float2 sg0[2], sg1[2], tsg[2];
    #pragma unroll
    for (int k = 0; k < 2; ++k) {
        const int c = c0 + k;
        b[k]  = c / QCHUNKS;
        qb[k] = (c - b[k] * QCHUNKS) * RPC + RPW * warp;
        L[k]  = lengths[b[k]];
        const int q0 = qb[k];
        sg0[k] = (q0 < NQ)     ? ((const float2*)pred_seg)[(size_t)b[k] * NQ + q0]
                               : make_float2(0.f, 0.f);
        sg1[k] = (q0 + 1 < NQ) ? ((const float2*)pred_seg)[(size_t)b[k] * NQ + q0 + 1]
                               : make_float2(0.f, 0.f);
        const int idx = b[k] * NT + lane;
        tsg[k] = ((const float2*)tgt_seg)[idx];
        lab[k] = is64 ? labels32[2 * idx] : labels32[idx];
    }

    // ---- compute one chunk from smem buffer p ----
    auto compute = [&](int k, int p) {
        const int q0 = qb[k];
        const int q1 = q0 + 1;
        const bool v0 = q0 < NQ;
        const bool v1 = q1 < NQ;
        if (!v0) return;

        const float*  row0 = s_rows[p][warp][0];
        const float*  row1 = s_rows[p][warp][1];
        const float4* r40  = (const float4*)row0;
        const float4* r41  = (const float4*)row1;

        // label gathers issued early (LDS latency overlaps the exp chain)
        const float g0 = row0[lab[k]];
        const float g1 = row1[lab[k]];

        // interleaved exps + denominators for both rows (ILP)
        float4 x0 = r40[lane];
        float4 x1 = r41[lane];
        float4 e;
        e.x = __expf(x0.x); e.y = __expf(x0.y);
        e.z = __expf(x0.z); e.w = __expf(x0.w);
        float s0 = (e.x + e.y) + (e.z + e.w);
        e.x = __expf(x1.x); e.y = __expf(x1.y);
        e.z = __expf(x1.z); e.w = __expf(x1.w);
        float s1 = (e.x + e.y) + (e.z + e.w);
        const float eg0 = __expf(g0);
        const float eg1 = __expf(g1);
        if (lane < 18) {
            float4 y0 = r40[lane + 32];
            float4 y1 = r41[lane + 32];
            e.x = __expf(y0.x); e.y = __expf(y0.y);
            e.z = __expf(y0.z); e.w = __expf(y0.w);
            s0 += (e.x + e.y) + (e.z + e.w);
            e.x = __expf(y1.x); e.y = __expf(y1.y);
            e.z = __expf(y1.z); e.w = __expf(y1.w);
            s1 += (e.x + e.y) + (e.z + e.w);
        }
        #pragma unroll
        for (int off = 16; off; off >>= 1) {
            s0 += __shfl_xor_sync(0xffffffffu, s0, off);
            s1 += __shfl_xor_sync(0xffffffffu, s1, off);
        }
        const float cls0 = -__fdividef(eg0, s0);
        const float cls1 = -__fdividef(eg1, s1);

        // target scaled once per chunk
        const float Lb  = L[k];
        const float tc  = tsg[k].x, tw = tsg[k].y;
        const float tcs = tc * Lb,  tws = tw * Lb;
        const float s2  = tcs - 0.5f * tws;
        const float e2  = tcs + 0.5f * tws;
        const float tlen = e2 - s2;

        {   // row q0
            const float cq = sg0[k].x, wq = sg0[k].y;
            const float cqs = cq * Lb, wqs = wq * Lb;
            const float a = cqs - 0.5f * wqs;
            const float z = cqs + 0.5f * wqs;
            float inter = fmaxf(fminf(z, e2) - fmaxf(a, s2), 0.f);
            const float uni = (z - a) + tlen - inter;
            const float enc = fmaxf(z, e2) - fminf(a, s2);
            const float giou = __fdividef(inter, uni)
                             - __fdividef(enc - uni, enc);
            out[((size_t)b[k] * NQ + q0) * NT + lane] =
                fabsf(cq - tc) + fabsf(wq - tw) + cls0 - giou;
        }
        if (v1) {   // row q1
            const float cq = sg1[k].x, wq = sg1[k].y;
            const float cqs = cq * Lb, wqs = wq * Lb;
            const float a = cqs - 0.5f * wqs;
            const float z = cqs + 0.5f * wqs;
            float inter = fmaxf(fminf(z, e2) - fmaxf(a, s2), 0.f);
            const float uni = (z - a) + tlen - inter;
            const float enc = fmaxf(z, e2) - fminf(a, s2);
            const float giou = __fdividef(inter, uni)
                             - __fdividef(enc - uni, enc);
            out[((size_t)b[k] * NQ + q1) * NT + lane] =
                fabsf(cq - tc) + fabsf(wq - tw) + cls1 - giou;
        }
    };

    // ---- two-stage drain ----
    asm volatile("cp.async.wait_group 1;\n" ::: "memory");
    __syncwarp();
    compute(0, 0);
    asm volatile("cp.async.wait_group 0;\n" ::: "memory");
    __syncwarp();
    compute(1, 1);
}

extern "C" void kernel_launch(void* const* d_in, const int* in_sizes, int n_in,
                              void* d_out, int out_size)
{
    const float* logits   = (const float*)d_in[0];
    const float* pred_seg = (const float*)d_in[1];
    const float* tgt_seg  = (const float*)d_in[2];
    const float* lengths  = (const float*)d_in[3];
    const int*   labels   = (const int*)d_in[4];
    float*       out      = (float*)d_out;

    matcher_kernel<<<GRID, THREADS>>>(logits, pred_seg, tgt_seg, lengths,
                                      labels, out);
}